// round 12
// baseline (speedup 1.0000x reference)
#include <cuda_runtime.h>
#include <cuda_bf16.h>
#include <mma.h>
#include <math.h>
#include <stdint.h>

using namespace nvcuda;

#define TT   2048
#define DD   768
#define HH   12
#define DKK  64
#define FFD  2048
#define LL   12
#define VV   50304
#define KC   4
#define EPSF 1e-6f

// weight plane offsets (elements), [K,N] layout
#define W4      589824
#define WFF     1572864
#define OFF_WQ  0
#define OFF_WK  7077888
#define OFF_WV  14155776
#define OFF_WO  21233664
#define OFF_WG  28311552
#define OFF_WU  47185920
#define OFF_WD  66060288
#define OFF_LM  84934656
#define TOT_W   123568128

// ---------------- scratch ----------------
__device__ float g_h   [TT*DD];
__device__ float g_x   [TT*DD];
__device__ float g_q   [TT*DD];
__device__ float g_k   [TT*DD];
__device__ float g_v   [TT*DD];
__device__ float g_qc  [TT*DD];
__device__ float g_kc  [TT*DD];
__device__ float g_vc  [TT*DD];
__device__ float g_o   [TT*DD];
__device__ float g_beta[TT*HH];
__device__ float g_gate[TT*FFD];
__device__ float g_up  [TT*FFD];
__device__ float g_rowloss[TT];

__device__ __nv_bfloat16 g_whi[TOT_W];
__device__ __nv_bfloat16 g_wlo[TOT_W];
__device__ __nv_bfloat16 g_xhi[TT*DD],  g_xlo[TT*DD];
__device__ __nv_bfloat16 g_ohi[TT*DD],  g_olo[TT*DD];
__device__ __nv_bfloat16 g_ghi[TT*FFD], g_glo[TT*FFD];

// ---------------- helpers ----------------
__device__ __forceinline__ void split2(float v, __nv_bfloat16& hi, __nv_bfloat16& lo) {
    hi = __float2bfloat16(v);
    lo = __float2bfloat16(v - __bfloat162float(hi));
}
__device__ __forceinline__ uint32_t smem_u32(const void* p) {
    uint32_t a;
    asm("{ .reg .u64 t; cvta.to.shared.u64 t, %1; cvt.u32.u64 %0, t; }" : "=r"(a) : "l"(p));
    return a;
}
__device__ __forceinline__ void cpa16(uint32_t dst, const void* src) {
    asm volatile("cp.async.cg.shared.global [%0], [%1], 16;" :: "r"(dst), "l"(src));
}
__device__ __forceinline__ void cpa_commit() { asm volatile("cp.async.commit_group;" ::: "memory"); }
template <int NN> __device__ __forceinline__ void cpa_wait() {
    asm volatile("cp.async.wait_group %0;" :: "n"(NN) : "memory");
}

// fp32 -> bf16 hi/lo planes
__global__ void cvt_k(const float* __restrict__ src, __nv_bfloat16* __restrict__ hi,
                      __nv_bfloat16* __restrict__ lo, int n4) {
    int i = blockIdx.x * 256 + threadIdx.x;
    if (i >= n4) return;
    float4 v = ((const float4*)src)[i];
    __nv_bfloat16 h0, h1, h2, h3, l0, l1, l2, l3;
    split2(v.x, h0, l0); split2(v.y, h1, l1); split2(v.z, h2, l2); split2(v.w, h3, l3);
    ((__nv_bfloat162*)hi)[2*i]   = __nv_bfloat162(h0, h1);
    ((__nv_bfloat162*)hi)[2*i+1] = __nv_bfloat162(h2, h3);
    ((__nv_bfloat162*)lo)[2*i]   = __nv_bfloat162(l0, l1);
    ((__nv_bfloat162*)lo)[2*i+1] = __nv_bfloat162(l2, l3);
}

__global__ void embed_k(const int* __restrict__ idx, const float* __restrict__ emb,
                        float* __restrict__ h) {
    int i = blockIdx.x * 256 + threadIdx.x;
    if (i < TT * DD) {
        int t = i / DD, d = i - t * DD;
        h[i] = emb[(size_t)idx[t] * DD + d];
    }
}

__global__ void rmsnorm_k(const float* __restrict__ in, const float* __restrict__ w,
                          float* __restrict__ out,
                          __nv_bfloat16* __restrict__ ohi, __nv_bfloat16* __restrict__ olo) {
    int t = blockIdx.x;
    const float* row = in + (size_t)t * DD;
    __shared__ float red[256];
    float s = 0.f;
    for (int i = threadIdx.x; i < DD; i += 256) { float v = row[i]; s += v * v; }
    red[threadIdx.x] = s; __syncthreads();
    for (int off = 128; off > 0; off >>= 1) {
        if (threadIdx.x < off) red[threadIdx.x] += red[threadIdx.x + off];
        __syncthreads();
    }
    float scale = rsqrtf(red[0] / (float)DD + EPSF);
    for (int i = threadIdx.x; i < DD; i += 256) {
        float v = row[i] * scale * w[i];
        size_t o = (size_t)t * DD + i;
        if (out) out[o] = v;
        __nv_bfloat16 hi, lo; split2(v, hi, lo);
        ohi[o] = hi; olo[o] = lo;
    }
}

// ---------------- cp.async split-bf16 GEMM, warp tile 64x64 ----------------
// BM=128 BN=128 BK=32, 128 threads (4 warps, 2x2), 2 CTAs/SM, 2-stage pipeline.
#define LDAe 40
#define LDBe 136
#define A_PL (128 * LDAe * 2)          // 10240 B per plane
#define B_PL (32 * LDBe * 2)           // 8704 B per plane
#define ST_AH 0
#define ST_AL (A_PL)
#define ST_BH (2 * A_PL)
#define ST_BL (2 * A_PL + B_PL)
#define STAGE_B (2 * A_PL + 2 * B_PL)  // 37888 B
#define SMEM_GEMM (2 * STAGE_B)        // 75776 B

template <bool ACC>
__global__ __launch_bounds__(128, 2) void gemm_bf(
    const __nv_bfloat16* __restrict__ Ah, const __nv_bfloat16* __restrict__ Al,
    const __nv_bfloat16* __restrict__ Bh0, const __nv_bfloat16* __restrict__ Bh1, const __nv_bfloat16* __restrict__ Bh2,
    const __nv_bfloat16* __restrict__ Bl0, const __nv_bfloat16* __restrict__ Bl1, const __nv_bfloat16* __restrict__ Bl2,
    float* __restrict__ C0, float* __restrict__ C1, float* __restrict__ C2,
    int M, int N, int K) {
    extern __shared__ char smem[];
    const __nv_bfloat16* Bh = (blockIdx.z == 0) ? Bh0 : (blockIdx.z == 1) ? Bh1 : Bh2;
    const __nv_bfloat16* Bl = (blockIdx.z == 0) ? Bl0 : (blockIdx.z == 1) ? Bl1 : Bl2;
    float*               C  = (blockIdx.z == 0) ? C0  : (blockIdx.z == 1) ? C1  : C2;

    const int bm = blockIdx.x * 128;
    const int bn = blockIdx.y * 128;
    const int tid = threadIdx.x;
    const int warp = tid >> 5;
    const int wm = warp >> 1;        // 0..1 -> 64-row slab
    const int wn = warp & 1;         // 0..1 -> 64-col slab

    const uint32_t sb = smem_u32(smem);

    // A copy: row tid (0..127), 4 x 16B chunks (32 elems)
    const int rowA = tid;
    // B copy: row tid>>2 (0..31), col (tid&3)*32, 4 x 16B chunks
    const int rowB = tid >> 2, cbB = (tid & 3) * 32;

    const __nv_bfloat16* gAh = Ah + (size_t)(bm + rowA) * K;
    const __nv_bfloat16* gAl = Al + (size_t)(bm + rowA) * K;
    const __nv_bfloat16* gBh = Bh + (size_t)rowB * N + bn + cbB;
    const __nv_bfloat16* gBl = Bl + (size_t)rowB * N + bn + cbB;

    const uint32_t dA = (uint32_t)(rowA * LDAe) * 2;
    const uint32_t dB = (uint32_t)(rowB * LDBe + cbB) * 2;

    wmma::fragment<wmma::accumulator, 16, 16, 16, float> acc[4][4];
#pragma unroll
    for (int mi = 0; mi < 4; mi++)
#pragma unroll
        for (int ni = 0; ni < 4; ni++) wmma::fill_fragment(acc[mi][ni], 0.f);

    auto issue = [&](int s, int k0) {
        uint32_t base = sb + s * STAGE_B;
#pragma unroll
        for (int c = 0; c < 4; c++) {
            cpa16(base + ST_AH + dA + c * 16, gAh + k0 + c * 8);
            cpa16(base + ST_AL + dA + c * 16, gAl + k0 + c * 8);
        }
        const __nv_bfloat16* b_h = gBh + (size_t)k0 * N;
        const __nv_bfloat16* b_l = gBl + (size_t)k0 * N;
#pragma unroll
        for (int c = 0; c < 4; c++) {
            cpa16(base + ST_BH + dB + c * 16, b_h + c * 8);
            cpa16(base + ST_BL + dB + c * 16, b_l + c * 8);
        }
        cpa_commit();
    };

    const int KT = K / 32;
    issue(0, 0);

    for (int kt = 0; kt < KT; kt++) {
        if (kt + 1 < KT) {
            issue((kt + 1) & 1, (kt + 1) * 32);
            cpa_wait<1>();
        } else {
            cpa_wait<0>();
        }
        __syncthreads();

        const int s = kt & 1;
        const __nv_bfloat16* pAh = (const __nv_bfloat16*)(smem + s * STAGE_B + ST_AH);
        const __nv_bfloat16* pAl = (const __nv_bfloat16*)(smem + s * STAGE_B + ST_AL);
        const __nv_bfloat16* pBh = (const __nv_bfloat16*)(smem + s * STAGE_B + ST_BH);
        const __nv_bfloat16* pBl = (const __nv_bfloat16*)(smem + s * STAGE_B + ST_BL);

#pragma unroll
        for (int kk = 0; kk < 32; kk += 16) {
            wmma::fragment<wmma::matrix_a, 16, 16, 16, __nv_bfloat16, wmma::row_major> ah[4], al[4];
#pragma unroll
            for (int mi = 0; mi < 4; mi++) {
                wmma::load_matrix_sync(ah[mi], pAh + (wm * 64 + mi * 16) * LDAe + kk, LDAe);
                wmma::load_matrix_sync(al[mi], pAl + (wm * 64 + mi * 16) * LDAe + kk, LDAe);
            }
#pragma unroll
            for (int ni = 0; ni < 4; ni++) {
                wmma::fragment<wmma::matrix_b, 16, 16, 16, __nv_bfloat16, wmma::row_major> bh, bl;
                wmma::load_matrix_sync(bh, pBh + kk * LDBe + wn * 64 + ni * 16, LDBe);
                wmma::load_matrix_sync(bl, pBl + kk * LDBe + wn * 64 + ni * 16, LDBe);
#pragma unroll
                for (int mi = 0; mi < 4; mi++) {
                    wmma::mma_sync(acc[mi][ni], ah[mi], bh, acc[mi][ni]);
                    wmma::mma_sync(acc[mi][ni], al[mi], bh, acc[mi][ni]);
                    wmma::mma_sync(acc[mi][ni], ah[mi], bl, acc[mi][ni]);
                }
            }
        }
        __syncthreads();
    }

#pragma unroll
    for (int mi = 0; mi < 4; mi++)
#pragma unroll
        for (int ni = 0; ni < 4; ni++) {
            float* cp = C + (size_t)(bm + wm * 64 + mi * 16) * N + bn + wn * 64 + ni * 16;
            if (ACC) {
                wmma::fragment<wmma::accumulator, 16, 16, 16, float> cf;
                wmma::load_matrix_sync(cf, cp, N, wmma::mem_row_major);
#pragma unroll
                for (int e = 0; e < cf.num_elements; e++) acc[mi][ni].x[e] += cf.x[e];
            }
            wmma::store_matrix_sync(cp, acc[mi][ni], N, wmma::mem_row_major);
        }
}

// beta: warp per (t,h)
__global__ void beta_k(const float* __restrict__ x, const float* __restrict__ Wb,
                       float* __restrict__ beta) {
    int g = blockIdx.x * 8 + (threadIdx.x >> 5);
    int lane = threadIdx.x & 31;
    if (g >= TT * HH) return;
    int t = g / HH, h = g - t * HH;
    const float* xr = x + (size_t)t * DD;
    float s = 0.f;
#pragma unroll
    for (int i = 0; i < DD / 32; i++) s += xr[lane + i * 32] * Wb[(lane + i * 32) * HH + h];
#pragma unroll
    for (int off = 16; off > 0; off >>= 1) s += __shfl_xor_sync(0xffffffffu, s, off);
    if (lane == 0) beta[g] = 1.f / (1.f + expf(-s));
}

__global__ void conv_silu_k(const float* __restrict__ x0, const float* __restrict__ x1,
                            const float* __restrict__ x2,
                            const float* __restrict__ w0, const float* __restrict__ w1,
                            const float* __restrict__ w2,
                            float* __restrict__ y0, float* __restrict__ y1,
                            float* __restrict__ y2) {
    const float* x = (blockIdx.y == 0) ? x0 : (blockIdx.y == 1) ? x1 : x2;
    const float* w = (blockIdx.y == 0) ? w0 : (blockIdx.y == 1) ? w1 : w2;
    float*       y = (blockIdx.y == 0) ? y0 : (blockIdx.y == 1) ? y1 : y2;
    int i = blockIdx.x * 256 + threadIdx.x;
    if (i >= TT * DD) return;
    int t = i / DD, d = i - t * DD;
    float acc = 0.f;
#pragma unroll
    for (int j = 0; j < KC; j++) {
        int tt = t - (KC - 1) + j;
        if (tt >= 0) acc += x[(size_t)tt * DD + d] * w[d * KC + j];
    }
    y[i] = acc / (1.f + expf(-acc));
}

__global__ void l2norm_k(float* __restrict__ a, float* __restrict__ b) {
    float* x = (blockIdx.y == 0) ? a : b;
    int g = blockIdx.x * blockDim.x + threadIdx.x;
    if (g >= TT * HH) return;
    int t = g / HH, h = g - t * HH;
    float* p = x + (size_t)t * DD + h * DKK;
    float s = 0.f;
#pragma unroll
    for (int i = 0; i < DKK; i++) s += p[i] * p[i];
    float sc = rsqrtf(s + EPSF);
#pragma unroll
    for (int i = 0; i < DKK; i++) p[i] *= sc;
}

__global__ void headnorm_k(const float* __restrict__ o, const float* __restrict__ w,
                           __nv_bfloat16* __restrict__ ohi, __nv_bfloat16* __restrict__ olo) {
    int g = blockIdx.x * blockDim.x + threadIdx.x;
    if (g >= TT * HH) return;
    int t = g / HH, h = g - t * HH;
    const float* p = o + (size_t)t * DD + h * DKK;
    float s = 0.f;
#pragma unroll
    for (int i = 0; i < DKK; i++) s += p[i] * p[i];
    float sc = rsqrtf(s / (float)DKK + EPSF);
#pragma unroll
    for (int i = 0; i < DKK; i++) {
        float v = p[i] * sc * w[i];
        __nv_bfloat16 hi, lo; split2(v, hi, lo);
        size_t idx = (size_t)t * DD + h * DKK + i;
        ohi[idx] = hi; olo[idx] = lo;
    }
}

// delta-rule: block per head, 64 threads, double-buffered publish, ONE barrier/step
__global__ void delta_k(const float* __restrict__ q, const float* __restrict__ k,
                        const float* __restrict__ v, const float* __restrict__ beta,
                        float* __restrict__ o) {
    const int h = blockIdx.x;
    const int j = threadIdx.x;
    float S[DKK];
#pragma unroll
    for (int i = 0; i < DKK; i++) S[i] = 0.f;
    __shared__ float qs[2][DKK], ks[2][DKK], vs[2][DKK];
    __shared__ float bs[2];

    // publish t=0 into buf 0
    {
        int b0 = h * DKK + j;
        qs[0][j] = q[b0]; ks[0][j] = k[b0]; vs[0][j] = v[b0];
        if (j == 0) bs[0] = beta[h];
    }
    __syncthreads();

    for (int t = 0; t < TT; t++) {
        const int cur = t & 1, nxt = cur ^ 1;
        // prefetch t+1 (gmem latency overlaps compute below)
        float qn = 0.f, kn = 0.f, vn = 0.f, bn_ = 0.f;
        if (t + 1 < TT) {
            int nb = (t + 1) * DD + h * DKK + j;
            qn = q[nb]; kn = k[nb]; vn = v[nb];
            if (j == 0) bn_ = beta[(t + 1) * HH + h];
        }
        float a0 = 0.f, a1 = 0.f, a2 = 0.f, a3 = 0.f;
#pragma unroll
        for (int i = 0; i < DKK; i += 4) {
            a0 += ks[cur][i + 0] * S[i + 0];
            a1 += ks[cur][i + 1] * S[i + 1];
            a2 += ks[cur][i + 2] * S[i + 2];
            a3 += ks[cur][i + 3] * S[i + 3];
        }
        float w = bs[cur] * (vs[cur][j] - ((a0 + a1) + (a2 + a3)));
        float o0 = 0.f, o1 = 0.f, o2 = 0.f, o3 = 0.f;
#pragma unroll
        for (int i = 0; i < DKK; i += 4) {
            S[i + 0] += ks[cur][i + 0] * w; o0 += qs[cur][i + 0] * S[i + 0];
            S[i + 1] += ks[cur][i + 1] * w; o1 += qs[cur][i + 1] * S[i + 1];
            S[i + 2] += ks[cur][i + 2] * w; o2 += qs[cur][i + 2] * S[i + 2];
            S[i + 3] += ks[cur][i + 3] * w; o3 += qs[cur][i + 3] * S[i + 3];
        }
        o[t * DD + h * DKK + j] = (o0 + o1) + (o2 + o3);
        // publish t+1 into the other buffer, then one barrier
        if (t + 1 < TT) {
            qs[nxt][j] = qn; ks[nxt][j] = kn; vs[nxt][j] = vn;
            if (j == 0) bs[nxt] = bn_;
        }
        __syncthreads();
    }
}

__global__ void silu_mul_k(const float* __restrict__ g, const float* __restrict__ u,
                           __nv_bfloat16* __restrict__ ghi, __nv_bfloat16* __restrict__ glo) {
    int i = blockIdx.x * 256 + threadIdx.x;
    if (i < TT * FFD) {
        float x = g[i];
        float r = (x / (1.f + expf(-x))) * u[i];
        __nv_bfloat16 hi, lo; split2(r, hi, lo);
        ghi[i] = hi; glo[i] = lo;
    }
}

__global__ void loss_rows_k(const float* __restrict__ logits, const int* __restrict__ tgt,
                            float* __restrict__ rowloss) {
    int t = blockIdx.x;
    const float* row = logits + (size_t)t * VV;
    __shared__ float red[256];
    float m = -1e30f;
    for (int i = threadIdx.x; i < VV; i += 256) m = fmaxf(m, row[i]);
    red[threadIdx.x] = m; __syncthreads();
    for (int off = 128; off > 0; off >>= 1) {
        if (threadIdx.x < off) red[threadIdx.x] = fmaxf(red[threadIdx.x], red[threadIdx.x + off]);
        __syncthreads();
    }
    m = red[0]; __syncthreads();
    float s = 0.f;
    for (int i = threadIdx.x; i < VV; i += 256) s += expf(row[i] - m);
    red[threadIdx.x] = s; __syncthreads();
    for (int off = 128; off > 0; off >>= 1) {
        if (threadIdx.x < off) red[threadIdx.x] += red[threadIdx.x + off];
        __syncthreads();
    }
    if (threadIdx.x == 0) {
        int tg = tgt[t];
        if (tg < 0) tg = 0;
        if (tg > VV - 1) tg = VV - 1;
        rowloss[t] = (m + logf(red[0])) - row[tg];
    }
}

__global__ void loss_final_k(const float* __restrict__ rowloss, float* __restrict__ out) {
    __shared__ float red[256];
    float s = 0.f;
    for (int i = threadIdx.x; i < TT; i += 256) s += rowloss[i];
    red[threadIdx.x] = s; __syncthreads();
    for (int off = 128; off > 0; off >>= 1) {
        if (threadIdx.x < off) red[threadIdx.x] += red[threadIdx.x + off];
        __syncthreads();
    }
    if (threadIdx.x == 0) out[0] = red[0] / (float)TT;
}

// ---------------- host launch ----------------

extern "C" void kernel_launch(void* const* d_in, const int* in_sizes, int n_in,
                              void* d_out, int out_size) {
    const int*   idx          = (const int*)d_in[0];
    const int*   targets      = (const int*)d_in[1];
    const float* embed        = (const float*)d_in[2];
    const float* Wq           = (const float*)d_in[3];
    const float* Wk           = (const float*)d_in[4];
    const float* Wv           = (const float*)d_in[5];
    const float* conv_q       = (const float*)d_in[6];
    const float* conv_k       = (const float*)d_in[7];
    const float* conv_v       = (const float*)d_in[8];
    const float* Wb           = (const float*)d_in[9];
    const float* o_norm_w     = (const float*)d_in[10];
    const float* Wo           = (const float*)d_in[11];
    const float* attn_norm_w  = (const float*)d_in[12];
    const float* mlp_norm_w   = (const float*)d_in[13];
    const float* Wgate        = (const float*)d_in[14];
    const float* Wup          = (const float*)d_in[15];
    const float* Wdown        = (const float*)d_in[16];
    const float* final_norm_w = (const float*)d_in[17];
    const float* lm_head      = (const float*)d_in[18];
    float* out = (float*)d_out;

    float *h, *x, *q, *k, *v, *qc, *kc, *vc, *o, *bet, *gate, *up, *rowloss;
    cudaGetSymbolAddress((void**)&h,   g_h);
    cudaGetSymbolAddress((void**)&x,   g_x);
    cudaGetSymbolAddress((void**)&q,   g_q);
    cudaGetSymbolAddress((void**)&k,   g_k);
    cudaGetSymbolAddress((void**)&v,   g_v);
    cudaGetSymbolAddress((void**)&qc,  g_qc);
    cudaGetSymbolAddress((void**)&kc,  g_kc);
    cudaGetSymbolAddress((void**)&vc,  g_vc);
    cudaGetSymbolAddress((void**)&o,   g_o);
    cudaGetSymbolAddress((void**)&bet, g_beta);
    cudaGetSymbolAddress((void**)&gate,g_gate);
    cudaGetSymbolAddress((void**)&up,  g_up);
    cudaGetSymbolAddress((void**)&rowloss, g_rowloss);

    __nv_bfloat16 *whi, *wlo, *xhi, *xlo, *ohi, *olo, *ghi, *glo;
    cudaGetSymbolAddress((void**)&whi, g_whi);
    cudaGetSymbolAddress((void**)&wlo, g_wlo);
    cudaGetSymbolAddress((void**)&xhi, g_xhi);
    cudaGetSymbolAddress((void**)&xlo, g_xlo);
    cudaGetSymbolAddress((void**)&ohi, g_ohi);
    cudaGetSymbolAddress((void**)&olo, g_olo);
    cudaGetSymbolAddress((void**)&ghi, g_ghi);
    cudaGetSymbolAddress((void**)&glo, g_glo);

    cudaFuncSetAttribute(gemm_bf<false>, cudaFuncAttributeMaxDynamicSharedMemorySize, SMEM_GEMM);
    cudaFuncSetAttribute(gemm_bf<true>,  cudaFuncAttributeMaxDynamicSharedMemorySize, SMEM_GEMM);

    // --- pre-convert all weights to bf16 hi/lo planes ([K,N] layout) ---
    {
        struct { const float* src; size_t off; int n; } segs[8] = {
            {Wq,     OFF_WQ, LL * W4},
            {Wk,     OFF_WK, LL * W4},
            {Wv,     OFF_WV, LL * W4},
            {Wo,     OFF_WO, LL * W4},
            {Wgate,  OFF_WG, LL * WFF},
            {Wup,    OFF_WU, LL * WFF},
            {Wdown,  OFF_WD, LL * WFF},
            {lm_head,OFF_LM, DD * VV},
        };
        for (int s = 0; s < 8; s++) {
            int n4 = segs[s].n / 4;
            cvt_k<<<(n4 + 255) / 256, 256>>>(segs[s].src, whi + segs[s].off, wlo + segs[s].off, n4);
        }
    }

    const int eltTD = (TT * DD + 255) / 256;
    const int eltTH = (TT * HH + 255) / 256;
    const int eltTF = (TT * FFD + 255) / 256;

    embed_k<<<eltTD, 256>>>(idx, embed, h);

    dim3 g_qkv(TT / 128, DD / 128, 3);
    dim3 g_one(TT / 128, DD / 128, 1);
    dim3 g_gu (TT / 128, FFD / 128, 2);
    dim3 g_vcb(TT / 128, VV / 128, 1);
    dim3 g_conv(eltTD, 3);
    dim3 g_l2(eltTH, 2);

    for (int l = 0; l < LL; l++) {
        rmsnorm_k<<<TT, 256>>>(h, attn_norm_w + (size_t)l * DD, x, xhi, xlo);

        gemm_bf<false><<<g_qkv, 128, SMEM_GEMM>>>(xhi, xlo,
            whi + OFF_WQ + (size_t)l * W4, whi + OFF_WK + (size_t)l * W4, whi + OFF_WV + (size_t)l * W4,
            wlo + OFF_WQ + (size_t)l * W4, wlo + OFF_WK + (size_t)l * W4, wlo + OFF_WV + (size_t)l * W4,
            q, k, v, TT, DD, DD);
        beta_k<<<(TT * HH + 7) / 8, 256>>>(x, Wb + (size_t)l * DD * HH, bet);

        conv_silu_k<<<g_conv, 256>>>(q, k, v,
            conv_q + (size_t)l * DD * KC, conv_k + (size_t)l * DD * KC, conv_v + (size_t)l * DD * KC,
            qc, kc, vc);
        l2norm_k<<<g_l2, 256>>>(qc, kc);

        delta_k<<<HH, DKK>>>(qc, kc, vc, bet, o);
        headnorm_k<<<eltTH, 256>>>(o, o_norm_w + (size_t)l * DKK, ohi, olo);

        gemm_bf<true><<<g_one, 128, SMEM_GEMM>>>(ohi, olo,
            whi + OFF_WO + (size_t)l * W4, nullptr, nullptr,
            wlo + OFF_WO + (size_t)l * W4, nullptr, nullptr,
            h, nullptr, nullptr, TT, DD, DD);

        rmsnorm_k<<<TT, 256>>>(h, mlp_norm_w + (size_t)l * DD, x, xhi, xlo);
        gemm_bf<false><<<g_gu, 128, SMEM_GEMM>>>(xhi, xlo,
            whi + OFF_WG + (size_t)l * WFF, whi + OFF_WU + (size_t)l * WFF, nullptr,
            wlo + OFF_WG + (size_t)l * WFF, wlo + OFF_WU + (size_t)l * WFF, nullptr,
            gate, up, nullptr, TT, FFD, DD);
        silu_mul_k<<<eltTF, 256>>>(gate, up, ghi, glo);
        gemm_bf<true><<<g_one, 128, SMEM_GEMM>>>(ghi, glo,
            whi + OFF_WD + (size_t)l * WFF, nullptr, nullptr,
            wlo + OFF_WD + (size_t)l * WFF, nullptr, nullptr,
            h, nullptr, nullptr, TT, DD, FFD);
    }

    rmsnorm_k<<<TT, 256>>>(h, final_norm_w, nullptr, xhi, xlo);

    if ((long long)out_size >= (long long)TT * VV) {
        gemm_bf<false><<<g_vcb, 128, SMEM_GEMM>>>(xhi, xlo,
            whi + OFF_LM, nullptr, nullptr,
            wlo + OFF_LM, nullptr, nullptr,
            out, nullptr, nullptr, TT, VV, DD);
        loss_rows_k<<<TT, 256>>>(out, targets, rowloss);
        if ((long long)out_size > (long long)TT * VV)
            loss_final_k<<<1, 256>>>(rowloss, out + (size_t)TT * VV);
    }
}

// round 13
// speedup vs baseline: 1.2693x; 1.2693x over previous
#include <cuda_runtime.h>
#include <cuda_bf16.h>
#include <mma.h>
#include <math.h>
#include <stdint.h>

using namespace nvcuda;

#define TT   2048
#define DD   768
#define HH   12
#define DKK  64
#define FFD  2048
#define LL   12
#define VV   50304
#define KC   4
#define EPSF 1e-6f

// weight plane offsets (elements), [K,N] layout
#define W4      589824
#define WFF     1572864
#define OFF_WQ  0
#define OFF_WK  7077888
#define OFF_WV  14155776
#define OFF_WO  21233664
#define OFF_WG  28311552
#define OFF_WU  47185920
#define OFF_WD  66060288
#define OFF_LM  84934656
#define TOT_W   123568128

// ---------------- scratch ----------------
__device__ float g_h   [TT*DD];
__device__ float g_x   [TT*DD];
__device__ float g_q   [TT*DD];
__device__ float g_k   [TT*DD];
__device__ float g_v   [TT*DD];
__device__ float g_qc  [TT*DD];
__device__ float g_kc  [TT*DD];
__device__ float g_vc  [TT*DD];
__device__ float g_o   [TT*DD];
__device__ float g_beta[TT*HH];
__device__ float g_gate[TT*FFD];
__device__ float g_up  [TT*FFD];
__device__ float g_rowloss[TT];

__device__ __nv_bfloat16 g_whi[TOT_W];
__device__ __nv_bfloat16 g_wlo[TOT_W];
__device__ __nv_bfloat16 g_xhi[TT*DD],  g_xlo[TT*DD];
__device__ __nv_bfloat16 g_ohi[TT*DD],  g_olo[TT*DD];
__device__ __nv_bfloat16 g_ghi[TT*FFD], g_glo[TT*FFD];

// ---------------- helpers ----------------
__device__ __forceinline__ void split2(float v, __nv_bfloat16& hi, __nv_bfloat16& lo) {
    hi = __float2bfloat16(v);
    lo = __float2bfloat16(v - __bfloat162float(hi));
}
__device__ __forceinline__ uint32_t smem_u32(const void* p) {
    uint32_t a;
    asm("{ .reg .u64 t; cvta.to.shared.u64 t, %1; cvt.u32.u64 %0, t; }" : "=r"(a) : "l"(p));
    return a;
}
__device__ __forceinline__ void cpa16(uint32_t dst, const void* src) {
    asm volatile("cp.async.cg.shared.global [%0], [%1], 16;" :: "r"(dst), "l"(src));
}
__device__ __forceinline__ void cpa_commit() { asm volatile("cp.async.commit_group;" ::: "memory"); }
template <int NN> __device__ __forceinline__ void cpa_wait() {
    asm volatile("cp.async.wait_group %0;" :: "n"(NN) : "memory");
}

// fp32 -> bf16 hi/lo planes
__global__ void cvt_k(const float* __restrict__ src, __nv_bfloat16* __restrict__ hi,
                      __nv_bfloat16* __restrict__ lo, int n4) {
    int i = blockIdx.x * 256 + threadIdx.x;
    if (i >= n4) return;
    float4 v = ((const float4*)src)[i];
    __nv_bfloat16 h0, h1, h2, h3, l0, l1, l2, l3;
    split2(v.x, h0, l0); split2(v.y, h1, l1); split2(v.z, h2, l2); split2(v.w, h3, l3);
    ((__nv_bfloat162*)hi)[2*i]   = __nv_bfloat162(h0, h1);
    ((__nv_bfloat162*)hi)[2*i+1] = __nv_bfloat162(h2, h3);
    ((__nv_bfloat162*)lo)[2*i]   = __nv_bfloat162(l0, l1);
    ((__nv_bfloat162*)lo)[2*i+1] = __nv_bfloat162(l2, l3);
}

__global__ void embed_k(const int* __restrict__ idx, const float* __restrict__ emb,
                        float* __restrict__ h) {
    int i = blockIdx.x * 256 + threadIdx.x;
    if (i < TT * DD) {
        int t = i / DD, d = i - t * DD;
        h[i] = emb[(size_t)idx[t] * DD + d];
    }
}

__global__ void rmsnorm_k(const float* __restrict__ in, const float* __restrict__ w,
                          float* __restrict__ out,
                          __nv_bfloat16* __restrict__ ohi, __nv_bfloat16* __restrict__ olo) {
    int t = blockIdx.x;
    const float* row = in + (size_t)t * DD;
    __shared__ float red[256];
    float s = 0.f;
    for (int i = threadIdx.x; i < DD; i += 256) { float v = row[i]; s += v * v; }
    red[threadIdx.x] = s; __syncthreads();
    for (int off = 128; off > 0; off >>= 1) {
        if (threadIdx.x < off) red[threadIdx.x] += red[threadIdx.x + off];
        __syncthreads();
    }
    float scale = rsqrtf(red[0] / (float)DD + EPSF);
    for (int i = threadIdx.x; i < DD; i += 256) {
        float v = row[i] * scale * w[i];
        size_t o = (size_t)t * DD + i;
        if (out) out[o] = v;
        __nv_bfloat16 hi, lo; split2(v, hi, lo);
        ohi[o] = hi; olo[o] = lo;
    }
}

// ---------------- cp.async double-buffered split-bf16 GEMM (R8 config) ----------------
#define LDAe 40
#define LDBe 136
#define A_PL (128 * LDAe * 2)
#define B_PL (32 * LDBe * 2)
#define ST_AH 0
#define ST_AL (A_PL)
#define ST_BH (2 * A_PL)
#define ST_BL (2 * A_PL + B_PL)
#define STAGE_B (2 * A_PL + 2 * B_PL)
#define SMEM_GEMM (2 * STAGE_B)

template <bool ACC>
__global__ __launch_bounds__(256, 1) void gemm_bf(
    const __nv_bfloat16* __restrict__ Ah, const __nv_bfloat16* __restrict__ Al,
    const __nv_bfloat16* __restrict__ Bh0, const __nv_bfloat16* __restrict__ Bh1, const __nv_bfloat16* __restrict__ Bh2,
    const __nv_bfloat16* __restrict__ Bl0, const __nv_bfloat16* __restrict__ Bl1, const __nv_bfloat16* __restrict__ Bl2,
    float* __restrict__ C0, float* __restrict__ C1, float* __restrict__ C2,
    int M, int N, int K) {
    extern __shared__ char smem[];
    const __nv_bfloat16* Bh = (blockIdx.z == 0) ? Bh0 : (blockIdx.z == 1) ? Bh1 : Bh2;
    const __nv_bfloat16* Bl = (blockIdx.z == 0) ? Bl0 : (blockIdx.z == 1) ? Bl1 : Bl2;
    float*               C  = (blockIdx.z == 0) ? C0  : (blockIdx.z == 1) ? C1  : C2;

    const int bm = blockIdx.x * 128;
    const int bn = blockIdx.y * 128;
    const int tid = threadIdx.x;
    const int warp = tid >> 5;
    const int wm = warp >> 2;
    const int wn = warp & 3;

    const uint32_t sb = smem_u32(smem);

    const int rowA = tid >> 1, ca = (tid & 1) * 16;
    const int rowB = tid >> 3, cb = (tid & 7) * 16;

    const __nv_bfloat16* gAh = Ah + (size_t)(bm + rowA) * K + ca;
    const __nv_bfloat16* gAl = Al + (size_t)(bm + rowA) * K + ca;
    const __nv_bfloat16* gBh = Bh + (size_t)rowB * N + bn + cb;
    const __nv_bfloat16* gBl = Bl + (size_t)rowB * N + bn + cb;

    const uint32_t dAoff = (uint32_t)(rowA * LDAe + ca) * 2;
    const uint32_t dBoff = (uint32_t)(rowB * LDBe + cb) * 2;

    wmma::fragment<wmma::accumulator, 16, 16, 16, float> acc[4][2];
#pragma unroll
    for (int mi = 0; mi < 4; mi++)
#pragma unroll
        for (int ni = 0; ni < 2; ni++) wmma::fill_fragment(acc[mi][ni], 0.f);

    auto issue = [&](int s, int k0) {
        uint32_t base = sb + s * STAGE_B;
        cpa16(base + ST_AH + dAoff,      gAh + k0);
        cpa16(base + ST_AH + dAoff + 16, gAh + k0 + 8);
        cpa16(base + ST_AL + dAoff,      gAl + k0);
        cpa16(base + ST_AL + dAoff + 16, gAl + k0 + 8);
        cpa16(base + ST_BH + dBoff,      gBh + (size_t)k0 * N);
        cpa16(base + ST_BH + dBoff + 16, gBh + (size_t)k0 * N + 8);
        cpa16(base + ST_BL + dBoff,      gBl + (size_t)k0 * N);
        cpa16(base + ST_BL + dBoff + 16, gBl + (size_t)k0 * N + 8);
        cpa_commit();
    };

    const int KT = K / 32;
    issue(0, 0);

    for (int kt = 0; kt < KT; kt++) {
        if (kt + 1 < KT) {
            issue((kt + 1) & 1, (kt + 1) * 32);
            cpa_wait<1>();
        } else {
            cpa_wait<0>();
        }
        __syncthreads();

        const int s = kt & 1;
        const __nv_bfloat16* pAh = (const __nv_bfloat16*)(smem + s * STAGE_B + ST_AH);
        const __nv_bfloat16* pAl = (const __nv_bfloat16*)(smem + s * STAGE_B + ST_AL);
        const __nv_bfloat16* pBh = (const __nv_bfloat16*)(smem + s * STAGE_B + ST_BH);
        const __nv_bfloat16* pBl = (const __nv_bfloat16*)(smem + s * STAGE_B + ST_BL);

#pragma unroll
        for (int kk = 0; kk < 32; kk += 16) {
            wmma::fragment<wmma::matrix_a, 16, 16, 16, __nv_bfloat16, wmma::row_major> ah[4], al[4];
#pragma unroll
            for (int mi = 0; mi < 4; mi++) {
                wmma::load_matrix_sync(ah[mi], pAh + (wm * 64 + mi * 16) * LDAe + kk, LDAe);
                wmma::load_matrix_sync(al[mi], pAl + (wm * 64 + mi * 16) * LDAe + kk, LDAe);
            }
#pragma unroll
            for (int ni = 0; ni < 2; ni++) {
                wmma::fragment<wmma::matrix_b, 16, 16, 16, __nv_bfloat16, wmma::row_major> bh, bl;
                wmma::load_matrix_sync(bh, pBh + kk * LDBe + wn * 32 + ni * 16, LDBe);
                wmma::load_matrix_sync(bl, pBl + kk * LDBe + wn * 32 + ni * 16, LDBe);
#pragma unroll
                for (int mi = 0; mi < 4; mi++) {
                    wmma::mma_sync(acc[mi][ni], ah[mi], bh, acc[mi][ni]);
                    wmma::mma_sync(acc[mi][ni], al[mi], bh, acc[mi][ni]);
                    wmma::mma_sync(acc[mi][ni], ah[mi], bl, acc[mi][ni]);
                }
            }
        }
        __syncthreads();
    }

#pragma unroll
    for (int mi = 0; mi < 4; mi++)
#pragma unroll
        for (int ni = 0; ni < 2; ni++) {
            float* cp = C + (size_t)(bm + wm * 64 + mi * 16) * N + bn + wn * 32 + ni * 16;
            if (ACC) {
                wmma::fragment<wmma::accumulator, 16, 16, 16, float> cf;
                wmma::load_matrix_sync(cf, cp, N, wmma::mem_row_major);
#pragma unroll
                for (int e = 0; e < cf.num_elements; e++) acc[mi][ni].x[e] += cf.x[e];
            }
            wmma::store_matrix_sync(cp, acc[mi][ni], N, wmma::mem_row_major);
        }
}

// beta: warp per (t,h)
__global__ void beta_k(const float* __restrict__ x, const float* __restrict__ Wb,
                       float* __restrict__ beta) {
    int g = blockIdx.x * 8 + (threadIdx.x >> 5);
    int lane = threadIdx.x & 31;
    if (g >= TT * HH) return;
    int t = g / HH, h = g - t * HH;
    const float* xr = x + (size_t)t * DD;
    float s = 0.f;
#pragma unroll
    for (int i = 0; i < DD / 32; i++) s += xr[lane + i * 32] * Wb[(lane + i * 32) * HH + h];
#pragma unroll
    for (int off = 16; off > 0; off >>= 1) s += __shfl_xor_sync(0xffffffffu, s, off);
    if (lane == 0) beta[g] = 1.f / (1.f + expf(-s));
}

// fused conv+SiLU for q,k,v + l2norm for q,k; warp per (t,h), lane owns dims lane & lane+32
__global__ void convl2_k(const float* __restrict__ q, const float* __restrict__ k,
                         const float* __restrict__ v,
                         const float* __restrict__ wq, const float* __restrict__ wk,
                         const float* __restrict__ wv,
                         float* __restrict__ qo, float* __restrict__ ko,
                         float* __restrict__ vo) {
    int g = blockIdx.x * 8 + (threadIdx.x >> 5);
    int lane = threadIdx.x & 31;
    if (g >= TT * HH) return;
    int t = g / HH, h = g - t * HH;

    float acq[2], ack[2], acv[2];
#pragma unroll
    for (int e = 0; e < 2; e++) {
        int d = h * DKK + lane + e * 32;
        float aq = 0.f, ak = 0.f, av = 0.f;
#pragma unroll
        for (int j = 0; j < KC; j++) {
            int tt = t - (KC - 1) + j;
            if (tt >= 0) {
                size_t off = (size_t)tt * DD + d;
                aq += q[off] * wq[d * KC + j];
                ak += k[off] * wk[d * KC + j];
                av += v[off] * wv[d * KC + j];
            }
        }
        acq[e] = aq / (1.f + expf(-aq));
        ack[e] = ak / (1.f + expf(-ak));
        acv[e] = av / (1.f + expf(-av));
    }
    float sq = acq[0] * acq[0] + acq[1] * acq[1];
    float sk = ack[0] * ack[0] + ack[1] * ack[1];
#pragma unroll
    for (int off = 16; off > 0; off >>= 1) {
        sq += __shfl_xor_sync(0xffffffffu, sq, off);
        sk += __shfl_xor_sync(0xffffffffu, sk, off);
    }
    float scq = rsqrtf(sq + EPSF);
    float sck = rsqrtf(sk + EPSF);
#pragma unroll
    for (int e = 0; e < 2; e++) {
        size_t o = (size_t)t * DD + h * DKK + lane + e * 32;
        qo[o] = acq[e] * scq;
        ko[o] = ack[e] * sck;
        vo[o] = acv[e];
    }
}

__global__ void headnorm_k(const float* __restrict__ o, const float* __restrict__ w,
                           __nv_bfloat16* __restrict__ ohi, __nv_bfloat16* __restrict__ olo) {
    int g = blockIdx.x * blockDim.x + threadIdx.x;
    if (g >= TT * HH) return;
    int t = g / HH, h = g - t * HH;
    const float* p = o + (size_t)t * DD + h * DKK;
    float s = 0.f;
#pragma unroll
    for (int i = 0; i < DKK; i++) s += p[i] * p[i];
    float sc = rsqrtf(s / (float)DKK + EPSF);
#pragma unroll
    for (int i = 0; i < DKK; i++) {
        float v = p[i] * sc * w[i];
        __nv_bfloat16 hi, lo; split2(v, hi, lo);
        size_t idx = (size_t)t * DD + h * DKK + i;
        ohi[idx] = hi; olo[idx] = lo;
    }
}

// delta-rule: block per head, 128 threads; thread = (col, half) with EVEN/ODD intra-warp
// pairing: col = tid>>1, half = tid&1. Cross-half combine via shfl_xor(1). One barrier/step.
__global__ void delta_k(const float* __restrict__ q, const float* __restrict__ k,
                        const float* __restrict__ v, const float* __restrict__ beta,
                        float* __restrict__ o) {
    const int h = blockIdx.x;
    const int tid = threadIdx.x;
    const int col = tid >> 1;
    const int half = tid & 1;
    const int i0 = half * 32;

    float S[32];
#pragma unroll
    for (int i = 0; i < 32; i++) S[i] = 0.f;
    __shared__ float qs[2][DKK], ks[2][DKK], vs[2][DKK];
    __shared__ float bs[2];

    // publish t=0
    if (half == 0) {
        int b0 = h * DKK + col;
        qs[0][col] = q[b0]; ks[0][col] = k[b0];
    } else {
        int b0 = h * DKK + col;
        vs[0][col] = v[b0];
        if (tid == 1) bs[0] = beta[h];
    }
    __syncthreads();

    for (int t = 0; t < TT; t++) {
        const int cur = t & 1, nxt = cur ^ 1;
        // prefetch t+1
        float qn = 0.f, kn = 0.f, vn = 0.f, bn_ = 0.f;
        if (t + 1 < TT) {
            int nb = (t + 1) * DD + h * DKK + col;
            if (half == 0) { qn = q[nb]; kn = k[nb]; }
            else           { vn = v[nb]; if (tid == 1) bn_ = beta[(t + 1) * HH + h]; }
        }
        // load own half of k into regs (reused in both loops)
        float kr[32];
#pragma unroll
        for (int i = 0; i < 32; i += 4)
            *(float4*)&kr[i] = *(const float4*)&ks[cur][i0 + i];

        float a0 = 0.f, a1 = 0.f, a2 = 0.f, a3 = 0.f;
#pragma unroll
        for (int i = 0; i < 32; i += 4) {
            a0 += kr[i + 0] * S[i + 0];
            a1 += kr[i + 1] * S[i + 1];
            a2 += kr[i + 2] * S[i + 2];
            a3 += kr[i + 3] * S[i + 3];
        }
        float d = (a0 + a1) + (a2 + a3);
        d += __shfl_xor_sync(0xffffffffu, d, 1);
        float w = bs[cur] * (vs[cur][col] - d);

        float o0 = 0.f, o1 = 0.f, o2 = 0.f, o3 = 0.f;
#pragma unroll
        for (int i = 0; i < 32; i += 4) {
            float4 q4 = *(const float4*)&qs[cur][i0 + i];
            S[i + 0] += kr[i + 0] * w; o0 += q4.x * S[i + 0];
            S[i + 1] += kr[i + 1] * w; o1 += q4.y * S[i + 1];
            S[i + 2] += kr[i + 2] * w; o2 += q4.z * S[i + 2];
            S[i + 3] += kr[i + 3] * w; o3 += q4.w * S[i + 3];
        }
        float od = (o0 + o1) + (o2 + o3);
        od += __shfl_xor_sync(0xffffffffu, od, 1);
        if (half == 0) o[t * DD + h * DKK + col] = od;

        // publish t+1, single barrier
        if (t + 1 < TT) {
            if (half == 0) { qs[nxt][col] = qn; ks[nxt][col] = kn; }
            else           { vs[nxt][col] = vn; if (tid == 1) bs[nxt] = bn_; }
        }
        __syncthreads();
    }
}

__global__ void silu_mul_k(const float* __restrict__ g, const float* __restrict__ u,
                           __nv_bfloat16* __restrict__ ghi, __nv_bfloat16* __restrict__ glo) {
    int i = blockIdx.x * 256 + threadIdx.x;
    if (i < TT * FFD) {
        float x = g[i];
        float r = (x / (1.f + expf(-x))) * u[i];
        __nv_bfloat16 hi, lo; split2(r, hi, lo);
        ghi[i] = hi; glo[i] = lo;
    }
}

__global__ void loss_rows_k(const float* __restrict__ logits, const int* __restrict__ tgt,
                            float* __restrict__ rowloss) {
    int t = blockIdx.x;
    const float* row = logits + (size_t)t * VV;
    __shared__ float red[256];
    float m = -1e30f;
    for (int i = threadIdx.x; i < VV; i += 256) m = fmaxf(m, row[i]);
    red[threadIdx.x] = m; __syncthreads();
    for (int off = 128; off > 0; off >>= 1) {
        if (threadIdx.x < off) red[threadIdx.x] = fmaxf(red[threadIdx.x], red[threadIdx.x + off]);
        __syncthreads();
    }
    m = red[0]; __syncthreads();
    float s = 0.f;
    for (int i = threadIdx.x; i < VV; i += 256) s += expf(row[i] - m);
    red[threadIdx.x] = s; __syncthreads();
    for (int off = 128; off > 0; off >>= 1) {
        if (threadIdx.x < off) red[threadIdx.x] += red[threadIdx.x + off];
        __syncthreads();
    }
    if (threadIdx.x == 0) {
        int tg = tgt[t];
        if (tg < 0) tg = 0;
        if (tg > VV - 1) tg = VV - 1;
        rowloss[t] = (m + logf(red[0])) - row[tg];
    }
}

__global__ void loss_final_k(const float* __restrict__ rowloss, float* __restrict__ out) {
    __shared__ float red[256];
    float s = 0.f;
    for (int i = threadIdx.x; i < TT; i += 256) s += rowloss[i];
    red[threadIdx.x] = s; __syncthreads();
    for (int off = 128; off > 0; off >>= 1) {
        if (threadIdx.x < off) red[threadIdx.x] += red[threadIdx.x + off];
        __syncthreads();
    }
    if (threadIdx.x == 0) out[0] = red[0] / (float)TT;
}

// ---------------- host launch ----------------

extern "C" void kernel_launch(void* const* d_in, const int* in_sizes, int n_in,
                              void* d_out, int out_size) {
    const int*   idx          = (const int*)d_in[0];
    const int*   targets      = (const int*)d_in[1];
    const float* embed        = (const float*)d_in[2];
    const float* Wq           = (const float*)d_in[3];
    const float* Wk           = (const float*)d_in[4];
    const float* Wv           = (const float*)d_in[5];
    const float* conv_q       = (const float*)d_in[6];
    const float* conv_k       = (const float*)d_in[7];
    const float* conv_v       = (const float*)d_in[8];
    const float* Wb           = (const float*)d_in[9];
    const float* o_norm_w     = (const float*)d_in[10];
    const float* Wo           = (const float*)d_in[11];
    const float* attn_norm_w  = (const float*)d_in[12];
    const float* mlp_norm_w   = (const float*)d_in[13];
    const float* Wgate        = (const float*)d_in[14];
    const float* Wup          = (const float*)d_in[15];
    const float* Wdown        = (const float*)d_in[16];
    const float* final_norm_w = (const float*)d_in[17];
    const float* lm_head      = (const float*)d_in[18];
    float* out = (float*)d_out;

    float *h, *x, *q, *k, *v, *qc, *kc, *vc, *o, *bet, *gate, *up, *rowloss;
    cudaGetSymbolAddress((void**)&h,   g_h);
    cudaGetSymbolAddress((void**)&x,   g_x);
    cudaGetSymbolAddress((void**)&q,   g_q);
    cudaGetSymbolAddress((void**)&k,   g_k);
    cudaGetSymbolAddress((void**)&v,   g_v);
    cudaGetSymbolAddress((void**)&qc,  g_qc);
    cudaGetSymbolAddress((void**)&kc,  g_kc);
    cudaGetSymbolAddress((void**)&vc,  g_vc);
    cudaGetSymbolAddress((void**)&o,   g_o);
    cudaGetSymbolAddress((void**)&bet, g_beta);
    cudaGetSymbolAddress((void**)&gate,g_gate);
    cudaGetSymbolAddress((void**)&up,  g_up);
    cudaGetSymbolAddress((void**)&rowloss, g_rowloss);

    __nv_bfloat16 *whi, *wlo, *xhi, *xlo, *ohi, *olo, *ghi, *glo;
    cudaGetSymbolAddress((void**)&whi, g_whi);
    cudaGetSymbolAddress((void**)&wlo, g_wlo);
    cudaGetSymbolAddress((void**)&xhi, g_xhi);
    cudaGetSymbolAddress((void**)&xlo, g_xlo);
    cudaGetSymbolAddress((void**)&ohi, g_ohi);
    cudaGetSymbolAddress((void**)&olo, g_olo);
    cudaGetSymbolAddress((void**)&ghi, g_ghi);
    cudaGetSymbolAddress((void**)&glo, g_glo);

    cudaFuncSetAttribute(gemm_bf<false>, cudaFuncAttributeMaxDynamicSharedMemorySize, SMEM_GEMM);
    cudaFuncSetAttribute(gemm_bf<true>,  cudaFuncAttributeMaxDynamicSharedMemorySize, SMEM_GEMM);

    // --- pre-convert all weights to bf16 hi/lo planes ([K,N] layout) ---
    {
        struct { const float* src; size_t off; int n; } segs[8] = {
            {Wq,     OFF_WQ, LL * W4},
            {Wk,     OFF_WK, LL * W4},
            {Wv,     OFF_WV, LL * W4},
            {Wo,     OFF_WO, LL * W4},
            {Wgate,  OFF_WG, LL * WFF},
            {Wup,    OFF_WU, LL * WFF},
            {Wdown,  OFF_WD, LL * WFF},
            {lm_head,OFF_LM, DD * VV},
        };
        for (int s = 0; s < 8; s++) {
            int n4 = segs[s].n / 4;
            cvt_k<<<(n4 + 255) / 256, 256>>>(segs[s].src, whi + segs[s].off, wlo + segs[s].off, n4);
        }
    }

    const int eltTD = (TT * DD + 255) / 256;
    const int eltTH = (TT * HH + 255) / 256;
    const int eltTF = (TT * FFD + 255) / 256;

    embed_k<<<eltTD, 256>>>(idx, embed, h);

    dim3 g_qkv(TT / 128, DD / 128, 3);
    dim3 g_one(TT / 128, DD / 128, 1);
    dim3 g_gu (TT / 128, FFD / 128, 2);
    dim3 g_vcb(TT / 128, VV / 128, 1);
    const int gwarp = (TT * HH + 7) / 8;

    for (int l = 0; l < LL; l++) {
        rmsnorm_k<<<TT, 256>>>(h, attn_norm_w + (size_t)l * DD, x, xhi, xlo);

        gemm_bf<false><<<g_qkv, 256, SMEM_GEMM>>>(xhi, xlo,
            whi + OFF_WQ + (size_t)l * W4, whi + OFF_WK + (size_t)l * W4, whi + OFF_WV + (size_t)l * W4,
            wlo + OFF_WQ + (size_t)l * W4, wlo + OFF_WK + (size_t)l * W4, wlo + OFF_WV + (size_t)l * W4,
            q, k, v, TT, DD, DD);
        beta_k<<<gwarp, 256>>>(x, Wb + (size_t)l * DD * HH, bet);

        convl2_k<<<gwarp, 256>>>(q, k, v,
            conv_q + (size_t)l * DD * KC, conv_k + (size_t)l * DD * KC, conv_v + (size_t)l * DD * KC,
            qc, kc, vc);

        delta_k<<<HH, 128>>>(qc, kc, vc, bet, o);
        headnorm_k<<<eltTH, 256>>>(o, o_norm_w + (size_t)l * DKK, ohi, olo);

        gemm_bf<true><<<g_one, 256, SMEM_GEMM>>>(ohi, olo,
            whi + OFF_WO + (size_t)l * W4, nullptr, nullptr,
            wlo + OFF_WO + (size_t)l * W4, nullptr, nullptr,
            h, nullptr, nullptr, TT, DD, DD);

        rmsnorm_k<<<TT, 256>>>(h, mlp_norm_w + (size_t)l * DD, x, xhi, xlo);
        gemm_bf<false><<<g_gu, 256, SMEM_GEMM>>>(xhi, xlo,
            whi + OFF_WG + (size_t)l * WFF, whi + OFF_WU + (size_t)l * WFF, nullptr,
            wlo + OFF_WG + (size_t)l * WFF, wlo + OFF_WU + (size_t)l * WFF, nullptr,
            gate, up, nullptr, TT, FFD, DD);
        silu_mul_k<<<eltTF, 256>>>(gate, up, ghi, glo);
        gemm_bf<true><<<g_one, 256, SMEM_GEMM>>>(ghi, glo,
            whi + OFF_WD + (size_t)l * WFF, nullptr, nullptr,
            wlo + OFF_WD + (size_t)l * WFF, nullptr, nullptr,
            h, nullptr, nullptr, TT, DD, FFD);
    }

    rmsnorm_k<<<TT, 256>>>(h, final_norm_w, nullptr, xhi, xlo);

    if ((long long)out_size >= (long long)TT * VV) {
        gemm_bf<false><<<g_vcb, 256, SMEM_GEMM>>>(xhi, xlo,
            whi + OFF_LM, nullptr, nullptr,
            wlo + OFF_LM, nullptr, nullptr,
            out, nullptr, nullptr, TT, VV, DD);
        loss_rows_k<<<TT, 256>>>(out, targets, rowloss);
        if ((long long)out_size > (long long)TT * VV)
            loss_final_k<<<1, 256>>>(rowloss, out + (size_t)TT * VV);
    }
}

// round 14
// speedup vs baseline: 1.4876x; 1.1720x over previous
#include <cuda_runtime.h>
#include <cuda_bf16.h>
#include <mma.h>
#include <math.h>
#include <stdint.h>

using namespace nvcuda;

#define TT   2048
#define DD   768
#define HH   12
#define DKK  64
#define FFD  2048
#define LL   12
#define VV   50304
#define KC   4
#define EPSF 1e-6f
#define CH   64
#define NCH  (TT / CH)   // 32

// weight plane offsets (elements), [K,N] layout
#define W4      589824
#define WFF     1572864
#define OFF_WQ  0
#define OFF_WK  7077888
#define OFF_WV  14155776
#define OFF_WO  21233664
#define OFF_WG  28311552
#define OFF_WU  47185920
#define OFF_WD  66060288
#define OFF_LM  84934656
#define TOT_W   123568128

// ---------------- scratch ----------------
__device__ float g_h   [TT*DD];
__device__ float g_x   [TT*DD];
__device__ float g_q   [TT*DD];
__device__ float g_k   [TT*DD];
__device__ float g_v   [TT*DD];
__device__ float g_qc  [TT*DD];
__device__ float g_kc  [TT*DD];
__device__ float g_vc  [TT*DD];
__device__ float g_o   [TT*DD];
__device__ float g_beta[TT*HH];
__device__ float g_gate[TT*FFD];
__device__ float g_up  [TT*FFD];
__device__ float g_rowloss[TT];
__device__ float g_Tm[HH*NCH*CH*CH];   // per (h,c) T = (I+A)^-1 diag(beta)
__device__ float g_Lm[HH*NCH*CH*CH];   // per (h,c) tril_incl(Q K^T)

__device__ __nv_bfloat16 g_whi[TOT_W];
__device__ __nv_bfloat16 g_wlo[TOT_W];
__device__ __nv_bfloat16 g_xhi[TT*DD],  g_xlo[TT*DD];
__device__ __nv_bfloat16 g_ohi[TT*DD],  g_olo[TT*DD];
__device__ __nv_bfloat16 g_ghi[TT*FFD], g_glo[TT*FFD];

// ---------------- helpers ----------------
__device__ __forceinline__ void split2(float v, __nv_bfloat16& hi, __nv_bfloat16& lo) {
    hi = __float2bfloat16(v);
    lo = __float2bfloat16(v - __bfloat162float(hi));
}
__device__ __forceinline__ uint32_t smem_u32(const void* p) {
    uint32_t a;
    asm("{ .reg .u64 t; cvta.to.shared.u64 t, %1; cvt.u32.u64 %0, t; }" : "=r"(a) : "l"(p));
    return a;
}
__device__ __forceinline__ void cpa16(uint32_t dst, const void* src) {
    asm volatile("cp.async.cg.shared.global [%0], [%1], 16;" :: "r"(dst), "l"(src));
}
__device__ __forceinline__ void cpa_commit() { asm volatile("cp.async.commit_group;" ::: "memory"); }
template <int NN> __device__ __forceinline__ void cpa_wait() {
    asm volatile("cp.async.wait_group %0;" :: "n"(NN) : "memory");
}

// fp32 -> bf16 hi/lo planes
__global__ void cvt_k(const float* __restrict__ src, __nv_bfloat16* __restrict__ hi,
                      __nv_bfloat16* __restrict__ lo, int n4) {
    int i = blockIdx.x * 256 + threadIdx.x;
    if (i >= n4) return;
    float4 v = ((const float4*)src)[i];
    __nv_bfloat16 h0, h1, h2, h3, l0, l1, l2, l3;
    split2(v.x, h0, l0); split2(v.y, h1, l1); split2(v.z, h2, l2); split2(v.w, h3, l3);
    ((__nv_bfloat162*)hi)[2*i]   = __nv_bfloat162(h0, h1);
    ((__nv_bfloat162*)hi)[2*i+1] = __nv_bfloat162(h2, h3);
    ((__nv_bfloat162*)lo)[2*i]   = __nv_bfloat162(l0, l1);
    ((__nv_bfloat162*)lo)[2*i+1] = __nv_bfloat162(l2, l3);
}

__global__ void embed_k(const int* __restrict__ idx, const float* __restrict__ emb,
                        float* __restrict__ h) {
    int i = blockIdx.x * 256 + threadIdx.x;
    if (i < TT * DD) {
        int t = i / DD, d = i - t * DD;
        h[i] = emb[(size_t)idx[t] * DD + d];
    }
}

__global__ void rmsnorm_k(const float* __restrict__ in, const float* __restrict__ w,
                          float* __restrict__ out,
                          __nv_bfloat16* __restrict__ ohi, __nv_bfloat16* __restrict__ olo) {
    int t = blockIdx.x;
    const float* row = in + (size_t)t * DD;
    __shared__ float red[256];
    float s = 0.f;
    for (int i = threadIdx.x; i < DD; i += 256) { float v = row[i]; s += v * v; }
    red[threadIdx.x] = s; __syncthreads();
    for (int off = 128; off > 0; off >>= 1) {
        if (threadIdx.x < off) red[threadIdx.x] += red[threadIdx.x + off];
        __syncthreads();
    }
    float scale = rsqrtf(red[0] / (float)DD + EPSF);
    for (int i = threadIdx.x; i < DD; i += 256) {
        float v = row[i] * scale * w[i];
        size_t o = (size_t)t * DD + i;
        if (out) out[o] = v;
        __nv_bfloat16 hi, lo; split2(v, hi, lo);
        ohi[o] = hi; olo[o] = lo;
    }
}

// ---------------- cp.async double-buffered split-bf16 GEMM (R8 config) ----------------
#define LDAe 40
#define LDBe 136
#define A_PL (128 * LDAe * 2)
#define B_PL (32 * LDBe * 2)
#define ST_AH 0
#define ST_AL (A_PL)
#define ST_BH (2 * A_PL)
#define ST_BL (2 * A_PL + B_PL)
#define STAGE_B (2 * A_PL + 2 * B_PL)
#define SMEM_GEMM (2 * STAGE_B)

template <bool ACC>
__global__ __launch_bounds__(256, 1) void gemm_bf(
    const __nv_bfloat16* __restrict__ Ah, const __nv_bfloat16* __restrict__ Al,
    const __nv_bfloat16* __restrict__ Bh0, const __nv_bfloat16* __restrict__ Bh1, const __nv_bfloat16* __restrict__ Bh2,
    const __nv_bfloat16* __restrict__ Bl0, const __nv_bfloat16* __restrict__ Bl1, const __nv_bfloat16* __restrict__ Bl2,
    float* __restrict__ C0, float* __restrict__ C1, float* __restrict__ C2,
    int M, int N, int K) {
    extern __shared__ char smem[];
    const __nv_bfloat16* Bh = (blockIdx.z == 0) ? Bh0 : (blockIdx.z == 1) ? Bh1 : Bh2;
    const __nv_bfloat16* Bl = (blockIdx.z == 0) ? Bl0 : (blockIdx.z == 1) ? Bl1 : Bl2;
    float*               C  = (blockIdx.z == 0) ? C0  : (blockIdx.z == 1) ? C1  : C2;

    const int bm = blockIdx.x * 128;
    const int bn = blockIdx.y * 128;
    const int tid = threadIdx.x;
    const int warp = tid >> 5;
    const int wm = warp >> 2;
    const int wn = warp & 3;

    const uint32_t sb = smem_u32(smem);

    const int rowA = tid >> 1, ca = (tid & 1) * 16;
    const int rowB = tid >> 3, cb = (tid & 7) * 16;

    const __nv_bfloat16* gAh = Ah + (size_t)(bm + rowA) * K + ca;
    const __nv_bfloat16* gAl = Al + (size_t)(bm + rowA) * K + ca;
    const __nv_bfloat16* gBh = Bh + (size_t)rowB * N + bn + cb;
    const __nv_bfloat16* gBl = Bl + (size_t)rowB * N + bn + cb;

    const uint32_t dAoff = (uint32_t)(rowA * LDAe + ca) * 2;
    const uint32_t dBoff = (uint32_t)(rowB * LDBe + cb) * 2;

    wmma::fragment<wmma::accumulator, 16, 16, 16, float> acc[4][2];
#pragma unroll
    for (int mi = 0; mi < 4; mi++)
#pragma unroll
        for (int ni = 0; ni < 2; ni++) wmma::fill_fragment(acc[mi][ni], 0.f);

    auto issue = [&](int s, int k0) {
        uint32_t base = sb + s * STAGE_B;
        cpa16(base + ST_AH + dAoff,      gAh + k0);
        cpa16(base + ST_AH + dAoff + 16, gAh + k0 + 8);
        cpa16(base + ST_AL + dAoff,      gAl + k0);
        cpa16(base + ST_AL + dAoff + 16, gAl + k0 + 8);
        cpa16(base + ST_BH + dBoff,      gBh + (size_t)k0 * N);
        cpa16(base + ST_BH + dBoff + 16, gBh + (size_t)k0 * N + 8);
        cpa16(base + ST_BL + dBoff,      gBl + (size_t)k0 * N);
        cpa16(base + ST_BL + dBoff + 16, gBl + (size_t)k0 * N + 8);
        cpa_commit();
    };

    const int KT = K / 32;
    issue(0, 0);

    for (int kt = 0; kt < KT; kt++) {
        if (kt + 1 < KT) {
            issue((kt + 1) & 1, (kt + 1) * 32);
            cpa_wait<1>();
        } else {
            cpa_wait<0>();
        }
        __syncthreads();

        const int s = kt & 1;
        const __nv_bfloat16* pAh = (const __nv_bfloat16*)(smem + s * STAGE_B + ST_AH);
        const __nv_bfloat16* pAl = (const __nv_bfloat16*)(smem + s * STAGE_B + ST_AL);
        const __nv_bfloat16* pBh = (const __nv_bfloat16*)(smem + s * STAGE_B + ST_BH);
        const __nv_bfloat16* pBl = (const __nv_bfloat16*)(smem + s * STAGE_B + ST_BL);

#pragma unroll
        for (int kk = 0; kk < 32; kk += 16) {
            wmma::fragment<wmma::matrix_a, 16, 16, 16, __nv_bfloat16, wmma::row_major> ah[4], al[4];
#pragma unroll
            for (int mi = 0; mi < 4; mi++) {
                wmma::load_matrix_sync(ah[mi], pAh + (wm * 64 + mi * 16) * LDAe + kk, LDAe);
                wmma::load_matrix_sync(al[mi], pAl + (wm * 64 + mi * 16) * LDAe + kk, LDAe);
            }
#pragma unroll
            for (int ni = 0; ni < 2; ni++) {
                wmma::fragment<wmma::matrix_b, 16, 16, 16, __nv_bfloat16, wmma::row_major> bh, bl;
                wmma::load_matrix_sync(bh, pBh + kk * LDBe + wn * 32 + ni * 16, LDBe);
                wmma::load_matrix_sync(bl, pBl + kk * LDBe + wn * 32 + ni * 16, LDBe);
#pragma unroll
                for (int mi = 0; mi < 4; mi++) {
                    wmma::mma_sync(acc[mi][ni], ah[mi], bh, acc[mi][ni]);
                    wmma::mma_sync(acc[mi][ni], al[mi], bh, acc[mi][ni]);
                    wmma::mma_sync(acc[mi][ni], ah[mi], bl, acc[mi][ni]);
                }
            }
        }
        __syncthreads();
    }

#pragma unroll
    for (int mi = 0; mi < 4; mi++)
#pragma unroll
        for (int ni = 0; ni < 2; ni++) {
            float* cp = C + (size_t)(bm + wm * 64 + mi * 16) * N + bn + wn * 32 + ni * 16;
            if (ACC) {
                wmma::fragment<wmma::accumulator, 16, 16, 16, float> cf;
                wmma::load_matrix_sync(cf, cp, N, wmma::mem_row_major);
#pragma unroll
                for (int e = 0; e < cf.num_elements; e++) acc[mi][ni].x[e] += cf.x[e];
            }
            wmma::store_matrix_sync(cp, acc[mi][ni], N, wmma::mem_row_major);
        }
}

// beta: warp per (t,h)
__global__ void beta_k(const float* __restrict__ x, const float* __restrict__ Wb,
                       float* __restrict__ beta) {
    int g = blockIdx.x * 8 + (threadIdx.x >> 5);
    int lane = threadIdx.x & 31;
    if (g >= TT * HH) return;
    int t = g / HH, h = g - t * HH;
    const float* xr = x + (size_t)t * DD;
    float s = 0.f;
#pragma unroll
    for (int i = 0; i < DD / 32; i++) s += xr[lane + i * 32] * Wb[(lane + i * 32) * HH + h];
#pragma unroll
    for (int off = 16; off > 0; off >>= 1) s += __shfl_xor_sync(0xffffffffu, s, off);
    if (lane == 0) beta[g] = 1.f / (1.f + expf(-s));
}

__global__ void conv_silu_k(const float* __restrict__ x0, const float* __restrict__ x1,
                            const float* __restrict__ x2,
                            const float* __restrict__ w0, const float* __restrict__ w1,
                            const float* __restrict__ w2,
                            float* __restrict__ y0, float* __restrict__ y1,
                            float* __restrict__ y2) {
    const float* x = (blockIdx.y == 0) ? x0 : (blockIdx.y == 1) ? x1 : x2;
    const float* w = (blockIdx.y == 0) ? w0 : (blockIdx.y == 1) ? w1 : w2;
    float*       y = (blockIdx.y == 0) ? y0 : (blockIdx.y == 1) ? y1 : y2;
    int i = blockIdx.x * 256 + threadIdx.x;
    if (i >= TT * DD) return;
    int t = i / DD, d = i - t * DD;
    float acc = 0.f;
#pragma unroll
    for (int j = 0; j < KC; j++) {
        int tt = t - (KC - 1) + j;
        if (tt >= 0) acc += x[(size_t)tt * DD + d] * w[d * KC + j];
    }
    y[i] = acc / (1.f + expf(-acc));
}

__global__ void l2norm_k(float* __restrict__ a, float* __restrict__ b) {
    float* x = (blockIdx.y == 0) ? a : b;
    int g = blockIdx.x * blockDim.x + threadIdx.x;
    if (g >= TT * HH) return;
    int t = g / HH, h = g - t * HH;
    float* p = x + (size_t)t * DD + h * DKK;
    float s = 0.f;
#pragma unroll
    for (int i = 0; i < DKK; i++) s += p[i] * p[i];
    float sc = rsqrtf(s + EPSF);
#pragma unroll
    for (int i = 0; i < DKK; i++) p[i] *= sc;
}

__global__ void headnorm_k(const float* __restrict__ o, const float* __restrict__ w,
                           __nv_bfloat16* __restrict__ ohi, __nv_bfloat16* __restrict__ olo) {
    int g = blockIdx.x * blockDim.x + threadIdx.x;
    if (g >= TT * HH) return;
    int t = g / HH, h = g - t * HH;
    const float* p = o + (size_t)t * DD + h * DKK;
    float s = 0.f;
#pragma unroll
    for (int i = 0; i < DKK; i++) s += p[i] * p[i];
    float sc = rsqrtf(s / (float)DKK + EPSF);
#pragma unroll
    for (int i = 0; i < DKK; i++) {
        float v = p[i] * sc * w[i];
        __nv_bfloat16 hi, lo; split2(v, hi, lo);
        size_t idx = (size_t)t * DD + h * DKK + i;
        ohi[idx] = hi; olo[idx] = lo;
    }
}

// ---------------- chunked delta rule ----------------
// Phase 1 (parallel over (h, chunk)): A = strict_tril(diag(beta) K K^T);
// T = (I+A)^{-1} diag(beta); L = tril_incl(Q K^T).
#define P1_KS 0
#define P1_QS (64 * 65)
#define P1_A  (2 * 64 * 65)
#define P1_T  (3 * 64 * 65)
#define P1_B  (4 * 64 * 65)
#define SMEM_P1 ((4 * 64 * 65 + 64) * 4)

__global__ __launch_bounds__(256, 1) void delta_pre_k(
    const float* __restrict__ q, const float* __restrict__ k,
    const float* __restrict__ beta,
    float* __restrict__ Tm, float* __restrict__ Lm) {
    extern __shared__ float sm[];
    float* Ks  = sm + P1_KS;   // [64][65]
    float* Qs  = sm + P1_QS;
    float* Aa  = sm + P1_A;
    float* Tsh = sm + P1_T;
    float* bsh = sm + P1_B;
    const int c = blockIdx.x, h = blockIdx.y;
    const int tid = threadIdx.x;

    for (int idx = tid; idx < CH * DKK; idx += 256) {
        int t = idx >> 6, i = idx & 63;
        size_t g = (size_t)(c * CH + t) * DD + h * DKK + i;
        Ks[t * 65 + i] = k[g];
        Qs[t * 65 + i] = q[g];
    }
    if (tid < CH) bsh[tid] = beta[(c * CH + tid) * HH + h];
    __syncthreads();

    float* lb = Lm + ((size_t)h * NCH + c) * CH * CH;
    for (int idx = tid; idx < CH * CH; idx += 256) {
        int t = idx >> 6, s = idx & 63;
        float ak = 0.f, al = 0.f;
        if (s < t) {
            for (int i = 0; i < DKK; i++) ak += Ks[t * 65 + i] * Ks[s * 65 + i];
            ak *= bsh[t];
        }
        if (s <= t) {
            for (int i = 0; i < DKK; i++) al += Qs[t * 65 + i] * Ks[s * 65 + i];
        }
        Aa[t * 65 + s] = ak;
        lb[idx] = al;
    }
    __syncthreads();

    // forward substitution: Tsh[t][j] = beta_t*[t==j] - sum_{s<t} A[t][s] * Tsh[s][j]
    for (int t = 0; t < CH; t++) {
        if (tid < CH) {
            int j = tid;
            float acc = (t == j) ? bsh[t] : 0.f;
            for (int s = 0; s < t; s++) acc -= Aa[t * 65 + s] * Tsh[s * 65 + j];
            Tsh[t * 65 + j] = acc;
        }
        __syncthreads();
    }
    float* tb = Tm + ((size_t)h * NCH + c) * CH * CH;
    for (int idx = tid; idx < CH * CH; idx += 256)
        tb[idx] = Tsh[(idx >> 6) * 65 + (idx & 63)];
}

// Phase 2 (scan over chunks, block per head, 512 threads):
// U = V - K S0 ; W = T U ; O = Q S0 + L W ; S0 += K^T W
#define LD2 68
#define P2_S  0
#define P2_K  (1 * 64 * LD2)
#define P2_V  (2 * 64 * LD2)
#define P2_Q  (3 * 64 * LD2)
#define P2_T  (4 * 64 * LD2)
#define P2_L  (5 * 64 * LD2)
#define P2_U  (6 * 64 * LD2)
#define P2_W  (7 * 64 * LD2)
#define SMEM_P2 (8 * 64 * LD2 * 4)

__global__ __launch_bounds__(512, 1) void delta_scan_k(
    const float* __restrict__ q, const float* __restrict__ k,
    const float* __restrict__ v,
    const float* __restrict__ Tm, const float* __restrict__ Lm,
    float* __restrict__ o) {
    extern __shared__ float sm[];
    float* S  = sm + P2_S;
    float* Ks = sm + P2_K;
    float* Vs = sm + P2_V;
    float* Qs = sm + P2_Q;
    float* Ts = sm + P2_T;
    float* Ls = sm + P2_L;
    float* U  = sm + P2_U;
    float* W  = sm + P2_W;
    const int h = blockIdx.x;
    const int tid = threadIdx.x;
    const int tx = tid & 15, ty = tid >> 4;     // ty 0..31
    const int t0 = ty, t1 = ty + 32, j0 = tx * 4;

    for (int i = tid; i < 64 * LD2; i += 512) S[i] = 0.f;
    __syncthreads();

    for (int c = 0; c < NCH; c++) {
        for (int idx = tid; idx < CH * DKK; idx += 512) {
            int t = idx >> 6, i = idx & 63;
            size_t g = (size_t)(c * CH + t) * DD + h * DKK + i;
            Ks[t * LD2 + i] = k[g];
            Vs[t * LD2 + i] = v[g];
            Qs[t * LD2 + i] = q[g];
        }
        const float* tb = Tm + ((size_t)h * NCH + c) * CH * CH;
        const float* lb = Lm + ((size_t)h * NCH + c) * CH * CH;
        for (int idx = tid; idx < CH * CH; idx += 512) {
            Ts[(idx >> 6) * LD2 + (idx & 63)] = tb[idx];
            Ls[(idx >> 6) * LD2 + (idx & 63)] = lb[idx];
        }
        __syncthreads();

        // U = V - K S
        {
            float a00=0,a01=0,a02=0,a03=0,a10=0,a11=0,a12=0,a13=0;
#pragma unroll 16
            for (int i = 0; i < DKK; i++) {
                float k0 = Ks[t0 * LD2 + i], k1 = Ks[t1 * LD2 + i];
                float4 s4 = *(const float4*)&S[i * LD2 + j0];
                a00 += k0 * s4.x; a01 += k0 * s4.y; a02 += k0 * s4.z; a03 += k0 * s4.w;
                a10 += k1 * s4.x; a11 += k1 * s4.y; a12 += k1 * s4.z; a13 += k1 * s4.w;
            }
            float4 v0 = *(const float4*)&Vs[t0 * LD2 + j0];
            float4 v1 = *(const float4*)&Vs[t1 * LD2 + j0];
            *(float4*)&U[t0 * LD2 + j0] = make_float4(v0.x - a00, v0.y - a01, v0.z - a02, v0.w - a03);
            *(float4*)&U[t1 * LD2 + j0] = make_float4(v1.x - a10, v1.y - a11, v1.z - a12, v1.w - a13);
        }
        __syncthreads();

        // W = T U
        {
            float a00=0,a01=0,a02=0,a03=0,a10=0,a11=0,a12=0,a13=0;
#pragma unroll 16
            for (int s = 0; s < CH; s++) {
                float r0 = Ts[t0 * LD2 + s], r1 = Ts[t1 * LD2 + s];
                float4 u4 = *(const float4*)&U[s * LD2 + j0];
                a00 += r0 * u4.x; a01 += r0 * u4.y; a02 += r0 * u4.z; a03 += r0 * u4.w;
                a10 += r1 * u4.x; a11 += r1 * u4.y; a12 += r1 * u4.z; a13 += r1 * u4.w;
            }
            *(float4*)&W[t0 * LD2 + j0] = make_float4(a00, a01, a02, a03);
            *(float4*)&W[t1 * LD2 + j0] = make_float4(a10, a11, a12, a13);
        }
        __syncthreads();

        // O = Q S + L W  -> gmem
        {
            float a00=0,a01=0,a02=0,a03=0,a10=0,a11=0,a12=0,a13=0;
#pragma unroll 16
            for (int i = 0; i < DKK; i++) {
                float q0 = Qs[t0 * LD2 + i], q1 = Qs[t1 * LD2 + i];
                float4 s4 = *(const float4*)&S[i * LD2 + j0];
                a00 += q0 * s4.x; a01 += q0 * s4.y; a02 += q0 * s4.z; a03 += q0 * s4.w;
                a10 += q1 * s4.x; a11 += q1 * s4.y; a12 += q1 * s4.z; a13 += q1 * s4.w;
            }
#pragma unroll 16
            for (int s = 0; s < CH; s++) {
                float l0 = Ls[t0 * LD2 + s], l1 = Ls[t1 * LD2 + s];
                float4 w4 = *(const float4*)&W[s * LD2 + j0];
                a00 += l0 * w4.x; a01 += l0 * w4.y; a02 += l0 * w4.z; a03 += l0 * w4.w;
                a10 += l1 * w4.x; a11 += l1 * w4.y; a12 += l1 * w4.z; a13 += l1 * w4.w;
            }
            *(float4*)&o[(size_t)(c * CH + t0) * DD + h * DKK + j0] = make_float4(a00, a01, a02, a03);
            *(float4*)&o[(size_t)(c * CH + t1) * DD + h * DKK + j0] = make_float4(a10, a11, a12, a13);
        }
        __syncthreads();

        // S += K^T W   (i0 = ty, i1 = ty+32 rows of S)
        {
            float a00=0,a01=0,a02=0,a03=0,a10=0,a11=0,a12=0,a13=0;
#pragma unroll 16
            for (int t = 0; t < CH; t++) {
                float k0 = Ks[t * LD2 + t0], k1 = Ks[t * LD2 + t1];
                float4 w4 = *(const float4*)&W[t * LD2 + j0];
                a00 += k0 * w4.x; a01 += k0 * w4.y; a02 += k0 * w4.z; a03 += k0 * w4.w;
                a10 += k1 * w4.x; a11 += k1 * w4.y; a12 += k1 * w4.z; a13 += k1 * w4.w;
            }
            float4 s0 = *(const float4*)&S[t0 * LD2 + j0];
            float4 s1 = *(const float4*)&S[t1 * LD2 + j0];
            *(float4*)&S[t0 * LD2 + j0] = make_float4(s0.x + a00, s0.y + a01, s0.z + a02, s0.w + a03);
            *(float4*)&S[t1 * LD2 + j0] = make_float4(s1.x + a10, s1.y + a11, s1.z + a12, s1.w + a13);
        }
        __syncthreads();
    }
}

__global__ void silu_mul_k(const float* __restrict__ g, const float* __restrict__ u,
                           __nv_bfloat16* __restrict__ ghi, __nv_bfloat16* __restrict__ glo) {
    int i = blockIdx.x * 256 + threadIdx.x;
    if (i < TT * FFD) {
        float x = g[i];
        float r = (x / (1.f + expf(-x))) * u[i];
        __nv_bfloat16 hi, lo; split2(r, hi, lo);
        ghi[i] = hi; glo[i] = lo;
    }
}

__global__ void loss_rows_k(const float* __restrict__ logits, const int* __restrict__ tgt,
                            float* __restrict__ rowloss) {
    int t = blockIdx.x;
    const float* row = logits + (size_t)t * VV;
    __shared__ float red[256];
    float m = -1e30f;
    for (int i = threadIdx.x; i < VV; i += 256) m = fmaxf(m, row[i]);
    red[threadIdx.x] = m; __syncthreads();
    for (int off = 128; off > 0; off >>= 1) {
        if (threadIdx.x < off) red[threadIdx.x] = fmaxf(red[threadIdx.x], red[threadIdx.x + off]);
        __syncthreads();
    }
    m = red[0]; __syncthreads();
    float s = 0.f;
    for (int i = threadIdx.x; i < VV; i += 256) s += expf(row[i] - m);
    red[threadIdx.x] = s; __syncthreads();
    for (int off = 128; off > 0; off >>= 1) {
        if (threadIdx.x < off) red[threadIdx.x] += red[threadIdx.x + off];
        __syncthreads();
    }
    if (threadIdx.x == 0) {
        int tg = tgt[t];
        if (tg < 0) tg = 0;
        if (tg > VV - 1) tg = VV - 1;
        rowloss[t] = (m + logf(red[0])) - row[tg];
    }
}

__global__ void loss_final_k(const float* __restrict__ rowloss, float* __restrict__ out) {
    __shared__ float red[256];
    float s = 0.f;
    for (int i = threadIdx.x; i < TT; i += 256) s += rowloss[i];
    red[threadIdx.x] = s; __syncthreads();
    for (int off = 128; off > 0; off >>= 1) {
        if (threadIdx.x < off) red[threadIdx.x] += red[threadIdx.x + off];
        __syncthreads();
    }
    if (threadIdx.x == 0) out[0] = red[0] / (float)TT;
}

// ---------------- host launch ----------------

extern "C" void kernel_launch(void* const* d_in, const int* in_sizes, int n_in,
                              void* d_out, int out_size) {
    const int*   idx          = (const int*)d_in[0];
    const int*   targets      = (const int*)d_in[1];
    const float* embed        = (const float*)d_in[2];
    const float* Wq           = (const float*)d_in[3];
    const float* Wk           = (const float*)d_in[4];
    const float* Wv           = (const float*)d_in[5];
    const float* conv_q       = (const float*)d_in[6];
    const float* conv_k       = (const float*)d_in[7];
    const float* conv_v       = (const float*)d_in[8];
    const float* Wb           = (const float*)d_in[9];
    const float* o_norm_w     = (const float*)d_in[10];
    const float* Wo           = (const float*)d_in[11];
    const float* attn_norm_w  = (const float*)d_in[12];
    const float* mlp_norm_w   = (const float*)d_in[13];
    const float* Wgate        = (const float*)d_in[14];
    const float* Wup          = (const float*)d_in[15];
    const float* Wdown        = (const float*)d_in[16];
    const float* final_norm_w = (const float*)d_in[17];
    const float* lm_head      = (const float*)d_in[18];
    float* out = (float*)d_out;

    float *h, *x, *q, *k, *v, *qc, *kc, *vc, *o, *bet, *gate, *up, *rowloss, *Tm, *Lm;
    cudaGetSymbolAddress((void**)&h,   g_h);
    cudaGetSymbolAddress((void**)&x,   g_x);
    cudaGetSymbolAddress((void**)&q,   g_q);
    cudaGetSymbolAddress((void**)&k,   g_k);
    cudaGetSymbolAddress((void**)&v,   g_v);
    cudaGetSymbolAddress((void**)&qc,  g_qc);
    cudaGetSymbolAddress((void**)&kc,  g_kc);
    cudaGetSymbolAddress((void**)&vc,  g_vc);
    cudaGetSymbolAddress((void**)&o,   g_o);
    cudaGetSymbolAddress((void**)&bet, g_beta);
    cudaGetSymbolAddress((void**)&gate,g_gate);
    cudaGetSymbolAddress((void**)&up,  g_up);
    cudaGetSymbolAddress((void**)&rowloss, g_rowloss);
    cudaGetSymbolAddress((void**)&Tm,  g_Tm);
    cudaGetSymbolAddress((void**)&Lm,  g_Lm);

    __nv_bfloat16 *whi, *wlo, *xhi, *xlo, *ohi, *olo, *ghi, *glo;
    cudaGetSymbolAddress((void**)&whi, g_whi);
    cudaGetSymbolAddress((void**)&wlo, g_wlo);
    cudaGetSymbolAddress((void**)&xhi, g_xhi);
    cudaGetSymbolAddress((void**)&xlo, g_xlo);
    cudaGetSymbolAddress((void**)&ohi, g_ohi);
    cudaGetSymbolAddress((void**)&olo, g_olo);
    cudaGetSymbolAddress((void**)&ghi, g_ghi);
    cudaGetSymbolAddress((void**)&glo, g_glo);

    cudaFuncSetAttribute(gemm_bf<false>, cudaFuncAttributeMaxDynamicSharedMemorySize, SMEM_GEMM);
    cudaFuncSetAttribute(gemm_bf<true>,  cudaFuncAttributeMaxDynamicSharedMemorySize, SMEM_GEMM);
    cudaFuncSetAttribute(delta_pre_k,    cudaFuncAttributeMaxDynamicSharedMemorySize, SMEM_P1);
    cudaFuncSetAttribute(delta_scan_k,   cudaFuncAttributeMaxDynamicSharedMemorySize, SMEM_P2);

    // --- pre-convert all weights to bf16 hi/lo planes ([K,N] layout) ---
    {
        struct { const float* src; size_t off; int n; } segs[8] = {
            {Wq,     OFF_WQ, LL * W4},
            {Wk,     OFF_WK, LL * W4},
            {Wv,     OFF_WV, LL * W4},
            {Wv,     OFF_WV, 0},
            {Wgate,  OFF_WG, LL * WFF},
            {Wup,    OFF_WU, LL * WFF},
            {Wdown,  OFF_WD, LL * WFF},
            {lm_head,OFF_LM, DD * VV},
        };
        segs[3].src = Wo; segs[3].off = OFF_WO; segs[3].n = LL * W4;
        for (int s = 0; s < 8; s++) {
            int n4 = segs[s].n / 4;
            cvt_k<<<(n4 + 255) / 256, 256>>>(segs[s].src, whi + segs[s].off, wlo + segs[s].off, n4);
        }
    }

    const int eltTD = (TT * DD + 255) / 256;
    const int eltTH = (TT * HH + 255) / 256;
    const int eltTF = (TT * FFD + 255) / 256;

    embed_k<<<eltTD, 256>>>(idx, embed, h);

    dim3 g_qkv(TT / 128, DD / 128, 3);
    dim3 g_one(TT / 128, DD / 128, 1);
    dim3 g_gu (TT / 128, FFD / 128, 2);
    dim3 g_vcb(TT / 128, VV / 128, 1);
    dim3 g_conv(eltTD, 3);
    dim3 g_l2(eltTH, 2);
    dim3 g_pre(NCH, HH);

    for (int l = 0; l < LL; l++) {
        rmsnorm_k<<<TT, 256>>>(h, attn_norm_w + (size_t)l * DD, x, xhi, xlo);

        gemm_bf<false><<<g_qkv, 256, SMEM_GEMM>>>(xhi, xlo,
            whi + OFF_WQ + (size_t)l * W4, whi + OFF_WK + (size_t)l * W4, whi + OFF_WV + (size_t)l * W4,
            wlo + OFF_WQ + (size_t)l * W4, wlo + OFF_WK + (size_t)l * W4, wlo + OFF_WV + (size_t)l * W4,
            q, k, v, TT, DD, DD);
        beta_k<<<(TT * HH + 7) / 8, 256>>>(x, Wb + (size_t)l * DD * HH, bet);

        conv_silu_k<<<g_conv, 256>>>(q, k, v,
            conv_q + (size_t)l * DD * KC, conv_k + (size_t)l * DD * KC, conv_v + (size_t)l * DD * KC,
            qc, kc, vc);
        l2norm_k<<<g_l2, 256>>>(qc, kc);

        delta_pre_k<<<g_pre, 256, SMEM_P1>>>(qc, kc, bet, Tm, Lm);
        delta_scan_k<<<HH, 512, SMEM_P2>>>(qc, kc, vc, Tm, Lm, o);
        headnorm_k<<<eltTH, 256>>>(o, o_norm_w + (size_t)l * DKK, ohi, olo);

        gemm_bf<true><<<g_one, 256, SMEM_GEMM>>>(ohi, olo,
            whi + OFF_WO + (size_t)l * W4, nullptr, nullptr,
            wlo + OFF_WO + (size_t)l * W4, nullptr, nullptr,
            h, nullptr, nullptr, TT, DD, DD);

        rmsnorm_k<<<TT, 256>>>(h, mlp_norm_w + (size_t)l * DD, x, xhi, xlo);
        gemm_bf<false><<<g_gu, 256, SMEM_GEMM>>>(xhi, xlo,
            whi + OFF_WG + (size_t)l * WFF, whi + OFF_WU + (size_t)l * WFF, nullptr,
            wlo + OFF_WG + (size_t)l * WFF, wlo + OFF_WU + (size_t)l * WFF, nullptr,
            gate, up, nullptr, TT, FFD, DD);
        silu_mul_k<<<eltTF, 256>>>(gate, up, ghi, glo);
        gemm_bf<true><<<g_one, 256, SMEM_GEMM>>>(ghi, glo,
            whi + OFF_WD + (size_t)l * WFF, nullptr, nullptr,
            wlo + OFF_WD + (size_t)l * WFF, nullptr, nullptr,
            h, nullptr, nullptr, TT, DD, FFD);
    }

    rmsnorm_k<<<TT, 256>>>(h, final_norm_w, nullptr, xhi, xlo);

    if ((long long)out_size >= (long long)TT * VV) {
        gemm_bf<false><<<g_vcb, 256, SMEM_GEMM>>>(xhi, xlo,
            whi + OFF_LM, nullptr, nullptr,
            wlo + OFF_LM, nullptr, nullptr,
            out, nullptr, nullptr, TT, VV, DD);
        loss_rows_k<<<TT, 256>>>(out, targets, rowloss);
        if ((long long)out_size > (long long)TT * VV)
            loss_final_k<<<1, 256>>>(rowloss, out + (size_t)TT * VV);
    }
}